// round 12
// baseline (speedup 1.0000x reference)
#include <cuda_runtime.h>
#include <cstdint>

// Embedding gather via TMA bulk-copy pipeline (R7 fixed).
// out[t, :] = weights[ids[t], :]
// ids: 16384 int32, weights: [50257,1024] fp32 (4KB rows), out: [16384,1024] fp32.
//
// 8-stage smem ring per CTA, single driver thread.
//   loads:  cp.async.bulk g->s, mbarrier complete_tx, running LA=6 slots ahead
//   stores: cp.async.bulk s->g, one bulk_group per row
// Refill discipline (the R7 bug fix): buffer for load j=i+LA is (i+LA)&7 ==
// (i-2)&7, last read by store i-2. After committing store i, wait_group.read 2
// leaves at most stores {i-1, i} outstanding -> store i-2 has finished reading
// its smem buffer. So 6 loads + up to 3 stores stay in flight per CTA (24KB+),
// ~6 CTAs/SM -> ~150KB outstanding per SM with zero register pressure.

static constexpr int ROW_BYTES   = 4096;  // 1024 fp32
static constexpr int STAGES      = 8;
static constexpr int LA          = 6;     // load lookahead (= STAGES - 2)
static constexpr int TOK_PER_CTA = 16;

__device__ __forceinline__ void mbar_init(uint32_t addr) {
    asm volatile("mbarrier.init.shared::cta.b64 [%0], 1;" :: "r"(addr));
}
__device__ __forceinline__ void mbar_expect_tx(uint32_t addr, uint32_t bytes) {
    asm volatile("mbarrier.arrive.expect_tx.shared::cta.b64 _, [%0], %1;"
                 :: "r"(addr), "r"(bytes) : "memory");
}
__device__ __forceinline__ void mbar_wait(uint32_t addr, uint32_t parity) {
    asm volatile(
        "{\n\t"
        ".reg .pred P;\n\t"
        "WAIT_%=:\n\t"
        "mbarrier.try_wait.parity.shared::cta.b64 P, [%0], %1, 0x989680;\n\t"
        "@P bra.uni DONE_%=;\n\t"
        "bra.uni WAIT_%=;\n\t"
        "DONE_%=:\n\t"
        "}"
        :: "r"(addr), "r"(parity) : "memory");
}
__device__ __forceinline__ void bulk_g2s(uint32_t dst_smem, const void* src,
                                         uint32_t bytes, uint32_t mbar) {
    asm volatile(
        "cp.async.bulk.shared::cta.global.mbarrier::complete_tx::bytes "
        "[%0], [%1], %2, [%3];"
        :: "r"(dst_smem), "l"(src), "r"(bytes), "r"(mbar) : "memory");
}
__device__ __forceinline__ void bulk_s2g(void* dst, uint32_t src_smem, uint32_t bytes) {
    asm volatile(
        "cp.async.bulk.global.shared::cta.bulk_group [%0], [%1], %2;"
        :: "l"(dst), "r"(src_smem), "r"(bytes) : "memory");
}
__device__ __forceinline__ void bulk_commit() {
    asm volatile("cp.async.bulk.commit_group;" ::: "memory");
}
__device__ __forceinline__ void bulk_wait_read2() {
    asm volatile("cp.async.bulk.wait_group.read 2;" ::: "memory");
}
__device__ __forceinline__ void bulk_wait_all() {
    asm volatile("cp.async.bulk.wait_group 0;" ::: "memory");
}

__global__ void __launch_bounds__(32) embed_tma_kernel(
    const int* __restrict__ ids,
    const char* __restrict__ w,
    char* __restrict__ out,
    int n_tokens)
{
    __shared__ alignas(128) char buf[STAGES][ROW_BYTES];
    __shared__ alignas(8)  uint64_t mbar[STAGES];

    if (threadIdx.x != 0) return;   // single driver thread per CTA

    const int base = blockIdx.x * TOK_PER_CTA;
    int nt = n_tokens - base;
    if (nt <= 0) return;
    if (nt > TOK_PER_CTA) nt = TOK_PER_CTA;

    uint32_t buf_s[STAGES], mbar_s[STAGES];
    #pragma unroll
    for (int s = 0; s < STAGES; ++s) {
        buf_s[s]  = (uint32_t)__cvta_generic_to_shared(&buf[s][0]);
        mbar_s[s] = (uint32_t)__cvta_generic_to_shared(&mbar[s]);
        mbar_init(mbar_s[s]);
    }
    asm volatile("fence.proxy.async.shared::cta;" ::: "memory");

    // prologue: launch the first LA loads
    #pragma unroll
    for (int j = 0; j < LA; ++j) {
        if (j < nt) {
            int row = __ldg(ids + base + j);
            mbar_expect_tx(mbar_s[j], ROW_BYTES);
            bulk_g2s(buf_s[j], w + (size_t)row * ROW_BYTES, ROW_BYTES, mbar_s[j]);
        }
    }

    for (int i = 0; i < nt; ++i) {
        const int s = i & (STAGES - 1);
        // wait for load i
        mbar_wait(mbar_s[s], (i >> 3) & 1u);
        // stream row i out (its own bulk group)
        bulk_s2g(out + (size_t)(base + i) * ROW_BYTES, buf_s[s], ROW_BYTES);
        bulk_commit();
        // lagged refill: load i+LA into buffer (i+LA)&7 == (i-2)&7,
        // last read by store i-2, which wait_group.read 2 guarantees done.
        const int j = i + LA;
        if (j < nt) {
            bulk_wait_read2();
            int row = __ldg(ids + base + j);
            const int bs = j & (STAGES - 1);
            mbar_expect_tx(mbar_s[bs], ROW_BYTES);
            bulk_g2s(buf_s[bs], w + (size_t)row * ROW_BYTES, ROW_BYTES, mbar_s[bs]);
        }
    }
    bulk_wait_all();   // all stores complete before exit
}

extern "C" void kernel_launch(void* const* d_in, const int* in_sizes, int n_in,
                              void* d_out, int out_size)
{
    const int*  ids = (const int*)d_in[0];
    const char* w   = (const char*)d_in[1];
    char*       out = (char*)d_out;

    int n_tokens = in_sizes[0];                                   // 16384
    int blocks   = (n_tokens + TOK_PER_CTA - 1) / TOK_PER_CTA;    // 1024
    embed_tma_kernel<<<blocks, 32>>>(ids, w, out, n_tokens);
}

// round 13
// speedup vs baseline: 1.1220x; 1.1220x over previous
#include <cuda_runtime.h>
#include <cstdint>

// Embedding gather: out[t, :] = weights[ids[t], :]
// ids: 16384 int32, weights: [50257,1024] fp32, out: [16384,1024] fp32
//
// Convergence: 5 structurally different designs (LDG batch, deep batch, TMA
// ring x2, persistent pipeline) all land 17.9-18.5us at ~4TB/s DRAM; binder
// is DRAM service on ~64MB compulsory writes + small read-miss traffic.
// This is R4's winning geometry (block=256, 4 tokens/iter) with two tweaks:
//  - single-wave persistent grid (148*8 CTAs, grid-stride) to remove ~2.5
//    wave transitions (~2-3us of tail at 8 CTAs/SM);
//  - __stwt write-through stores: output never dirties L2, weight rows stay
//    resident across graph replays, no dirty-eviction in the write path.

static constexpr int ROW_F4 = 256;   // float4 per row (1024 floats)

__global__ void __launch_bounds__(256, 6) embed_gather_kernel(
    const int* __restrict__ ids,
    const float4* __restrict__ w,
    float4* __restrict__ out,
    int n_tokens)
{
    const int col    = threadIdx.x;        // 0..255: float4 column within row
    const int nchunk = n_tokens >> 2;      // 4 tokens per chunk (16384 % 4 == 0)

    for (int c = blockIdx.x; c < nchunk; c += gridDim.x) {
        const int t0 = c << 2;

        const int r0 = __ldg(ids + t0 + 0);
        const int r1 = __ldg(ids + t0 + 1);
        const int r2 = __ldg(ids + t0 + 2);
        const int r3 = __ldg(ids + t0 + 3);

        float4 v0 = __ldg(w + (size_t)r0 * ROW_F4 + col);
        float4 v1 = __ldg(w + (size_t)r1 * ROW_F4 + col);
        float4 v2 = __ldg(w + (size_t)r2 * ROW_F4 + col);
        float4 v3 = __ldg(w + (size_t)r3 * ROW_F4 + col);

        __stwt(out + (size_t)(t0 + 0) * ROW_F4 + col, v0);
        __stwt(out + (size_t)(t0 + 1) * ROW_F4 + col, v1);
        __stwt(out + (size_t)(t0 + 2) * ROW_F4 + col, v2);
        __stwt(out + (size_t)(t0 + 3) * ROW_F4 + col, v3);
    }
}

extern "C" void kernel_launch(void* const* d_in, const int* in_sizes, int n_in,
                              void* d_out, int out_size)
{
    const int*    ids = (const int*)d_in[0];
    const float4* w   = (const float4*)d_in[1];
    float4*       out = (float4*)d_out;

    int n_tokens = in_sizes[0];            // 16384
    int nchunk   = n_tokens >> 2;          // 4096

    int blocks = 148 * 8;                  // one full wave at 8 CTAs/SM
    if (blocks > nchunk) blocks = nchunk;

    embed_gather_kernel<<<blocks, 256>>>(ids, w, out, n_tokens);
}

// round 14
// speedup vs baseline: 1.2800x; 1.1409x over previous
#include <cuda_runtime.h>
#include <cstdint>

// Embedding gather: out[t, :] = weights[ids[t], :]
// ids: 16384 int32, weights: [50257,1024] fp32, out: [16384,1024] fp32
//
// FINAL (R4 config, empirical optimum). Convergence evidence: six designs
// (LDG batch x3 geometries, TMA ring x2, persistent pipeline) spanning
// occ 11-83%, regs 16-92, MLP_p1 1-8, and all three store policies
// (.cs / default / .wt) land 17.9-18.6us kernel at 3.9-4.1 TB/s DRAM.
// Binder: DRAM service rate on ~64MB compulsory coalesced writes + scattered
// 4KB read misses. This shape -- block=256 (one float4-column per thread),
// 4 tokens per block front-batched as 4 independent LDG.128 (MLP_p1=4),
// streaming .cs stores, grid 4096, regs=32, occ ~79% -- was never beaten.

static constexpr int ROW_F4      = 256;  // float4 per row (1024 floats)
static constexpr int TOK_PER_BLK = 4;

__global__ void __launch_bounds__(256) embed_gather_kernel(
    const int* __restrict__ ids,
    const float4* __restrict__ w,
    float4* __restrict__ out,
    int n_tokens)
{
    const int col  = threadIdx.x;                 // 0..255
    const int tok0 = blockIdx.x * TOK_PER_BLK;

    if (tok0 + TOK_PER_BLK <= n_tokens) {
        // fast path: fully unrolled, 4 independent gathers
        const int r0 = __ldg(ids + tok0 + 0);
        const int r1 = __ldg(ids + tok0 + 1);
        const int r2 = __ldg(ids + tok0 + 2);
        const int r3 = __ldg(ids + tok0 + 3);

        float4 v0 = __ldg(w + (size_t)r0 * ROW_F4 + col);
        float4 v1 = __ldg(w + (size_t)r1 * ROW_F4 + col);
        float4 v2 = __ldg(w + (size_t)r2 * ROW_F4 + col);
        float4 v3 = __ldg(w + (size_t)r3 * ROW_F4 + col);

        __stcs(out + (size_t)(tok0 + 0) * ROW_F4 + col, v0);
        __stcs(out + (size_t)(tok0 + 1) * ROW_F4 + col, v1);
        __stcs(out + (size_t)(tok0 + 2) * ROW_F4 + col, v2);
        __stcs(out + (size_t)(tok0 + 3) * ROW_F4 + col, v3);
    } else {
        for (int t = tok0; t < n_tokens; ++t) {
            int r = __ldg(ids + t);
            __stcs(out + (size_t)t * ROW_F4 + col,
                   __ldg(w + (size_t)r * ROW_F4 + col));
        }
    }
}

extern "C" void kernel_launch(void* const* d_in, const int* in_sizes, int n_in,
                              void* d_out, int out_size)
{
    const int*    ids = (const int*)d_in[0];
    const float4* w   = (const float4*)d_in[1];
    float4*       out = (float4*)d_out;

    int n_tokens = in_sizes[0];                       // 16384
    int blocks   = (n_tokens + TOK_PER_BLK - 1) / TOK_PER_BLK;  // 4096
    embed_gather_kernel<<<blocks, 256>>>(ids, w, out, n_tokens);
}

// round 15
// speedup vs baseline: 1.3050x; 1.0195x over previous
#include <cuda_runtime.h>
#include <cstdint>

// Embedding gather: out[t, :] = weights[ids[t], :]
// ids: 16384 int32, weights: [50257,1024] fp32, out: [16384,1024] fp32
//
// Last untested corner: high per-thread MLP *and* high occupancy at once.
// R8 (256thr x 8 loads -> 92 regs -> 2 CTAs/SM) showed deep batching kills
// occupancy at block=256. At block=128, the same 8-deep batch costs only
// ~6-7K regs/CTA -> ~8 CTAs/SM. Each thread handles two float4 columns
// (col, col+128) of 4 tokens: 8 independent front-batched LDG.128, stores
// grouped after. Streaming .cs stores as established. grid=4096.

static constexpr int ROW_F4      = 256;  // float4 per row (1024 floats)
static constexpr int TOK_PER_BLK = 4;

__global__ void __launch_bounds__(128) embed_gather_kernel(
    const int* __restrict__ ids,
    const float4* __restrict__ w,
    float4* __restrict__ out,
    int n_tokens)
{
    const int c0   = threadIdx.x;          // column 0..127
    const int c1   = threadIdx.x + 128;    // column 128..255
    const int tok0 = blockIdx.x * TOK_PER_BLK;

    if (tok0 + TOK_PER_BLK <= n_tokens) {
        const int r0 = __ldg(ids + tok0 + 0);
        const int r1 = __ldg(ids + tok0 + 1);
        const int r2 = __ldg(ids + tok0 + 2);
        const int r3 = __ldg(ids + tok0 + 3);

        // 8 independent gathers, front-batched
        float4 a0 = __ldg(w + (size_t)r0 * ROW_F4 + c0);
        float4 b0 = __ldg(w + (size_t)r0 * ROW_F4 + c1);
        float4 a1 = __ldg(w + (size_t)r1 * ROW_F4 + c0);
        float4 b1 = __ldg(w + (size_t)r1 * ROW_F4 + c1);
        float4 a2 = __ldg(w + (size_t)r2 * ROW_F4 + c0);
        float4 b2 = __ldg(w + (size_t)r2 * ROW_F4 + c1);
        float4 a3 = __ldg(w + (size_t)r3 * ROW_F4 + c0);
        float4 b3 = __ldg(w + (size_t)r3 * ROW_F4 + c1);

        __stcs(out + (size_t)(tok0 + 0) * ROW_F4 + c0, a0);
        __stcs(out + (size_t)(tok0 + 0) * ROW_F4 + c1, b0);
        __stcs(out + (size_t)(tok0 + 1) * ROW_F4 + c0, a1);
        __stcs(out + (size_t)(tok0 + 1) * ROW_F4 + c1, b1);
        __stcs(out + (size_t)(tok0 + 2) * ROW_F4 + c0, a2);
        __stcs(out + (size_t)(tok0 + 2) * ROW_F4 + c1, b2);
        __stcs(out + (size_t)(tok0 + 3) * ROW_F4 + c0, a3);
        __stcs(out + (size_t)(tok0 + 3) * ROW_F4 + c1, b3);
    } else {
        for (int t = tok0; t < n_tokens; ++t) {
            int r = __ldg(ids + t);
            __stcs(out + (size_t)t * ROW_F4 + c0, __ldg(w + (size_t)r * ROW_F4 + c0));
            __stcs(out + (size_t)t * ROW_F4 + c1, __ldg(w + (size_t)r * ROW_F4 + c1));
        }
    }
}

extern "C" void kernel_launch(void* const* d_in, const int* in_sizes, int n_in,
                              void* d_out, int out_size)
{
    const int*    ids = (const int*)d_in[0];
    const float4* w   = (const float4*)d_in[1];
    float4*       out = (float4*)d_out;

    int n_tokens = in_sizes[0];                                  // 16384
    int blocks   = (n_tokens + TOK_PER_BLK - 1) / TOK_PER_BLK;   // 4096
    embed_gather_kernel<<<blocks, 128>>>(ids, w, out, n_tokens);
}

// round 16
// speedup vs baseline: 1.3939x; 1.0682x over previous
#include <cuda_runtime.h>
#include <cstdint>

// Embedding gather: out[t, :] = weights[ids[t], :]
// ids: 16384 int32, weights: [50257,1024] fp32, out: [16384,1024] fp32
//
// R15 rerun with the register cap actually lifted: __launch_bounds__(128, 8)
// allows ~64 regs/thread (R15 silently capped at 32, interleaving the loads,
// same failure as R5). Each thread: two float4 columns (col, col+128) x 4
// tokens = 8 independent front-batched LDG.128 (MLP_p1=8), then 8 grouped
// .cs stores. 8 CTAs/SM x 128 thr -> occ ~50% with 2x R4's in-flight bytes.
// This is the last untested corner (MLP=8 + mid occupancy); if flat, the
// ~4TB/s DRAM plateau is confirmed as the wall and R4/R14 is final.

static constexpr int ROW_F4      = 256;  // float4 per row (1024 floats)
static constexpr int TOK_PER_BLK = 4;

__global__ void __launch_bounds__(128, 8) embed_gather_kernel(
    const int* __restrict__ ids,
    const float4* __restrict__ w,
    float4* __restrict__ out,
    int n_tokens)
{
    const int c0   = threadIdx.x;          // column 0..127
    const int c1   = threadIdx.x + 128;    // column 128..255
    const int tok0 = blockIdx.x * TOK_PER_BLK;

    if (tok0 + TOK_PER_BLK <= n_tokens) {
        const int r0 = __ldg(ids + tok0 + 0);
        const int r1 = __ldg(ids + tok0 + 1);
        const int r2 = __ldg(ids + tok0 + 2);
        const int r3 = __ldg(ids + tok0 + 3);

        // 8 independent gathers, front-batched
        float4 a0 = __ldg(w + (size_t)r0 * ROW_F4 + c0);
        float4 b0 = __ldg(w + (size_t)r0 * ROW_F4 + c1);
        float4 a1 = __ldg(w + (size_t)r1 * ROW_F4 + c0);
        float4 b1 = __ldg(w + (size_t)r1 * ROW_F4 + c1);
        float4 a2 = __ldg(w + (size_t)r2 * ROW_F4 + c0);
        float4 b2 = __ldg(w + (size_t)r2 * ROW_F4 + c1);
        float4 a3 = __ldg(w + (size_t)r3 * ROW_F4 + c0);
        float4 b3 = __ldg(w + (size_t)r3 * ROW_F4 + c1);

        __stcs(out + (size_t)(tok0 + 0) * ROW_F4 + c0, a0);
        __stcs(out + (size_t)(tok0 + 0) * ROW_F4 + c1, b0);
        __stcs(out + (size_t)(tok0 + 1) * ROW_F4 + c0, a1);
        __stcs(out + (size_t)(tok0 + 1) * ROW_F4 + c1, b1);
        __stcs(out + (size_t)(tok0 + 2) * ROW_F4 + c0, a2);
        __stcs(out + (size_t)(tok0 + 2) * ROW_F4 + c1, b2);
        __stcs(out + (size_t)(tok0 + 3) * ROW_F4 + c0, a3);
        __stcs(out + (size_t)(tok0 + 3) * ROW_F4 + c1, b3);
    } else {
        for (int t = tok0; t < n_tokens; ++t) {
            int r = __ldg(ids + t);
            __stcs(out + (size_t)t * ROW_F4 + c0, __ldg(w + (size_t)r * ROW_F4 + c0));
            __stcs(out + (size_t)t * ROW_F4 + c1, __ldg(w + (size_t)r * ROW_F4 + c1));
        }
    }
}

extern "C" void kernel_launch(void* const* d_in, const int* in_sizes, int n_in,
                              void* d_out, int out_size)
{
    const int*    ids = (const int*)d_in[0];
    const float4* w   = (const float4*)d_in[1];
    float4*       out = (float4*)d_out;

    int n_tokens = in_sizes[0];                                  // 16384
    int blocks   = (n_tokens + TOK_PER_BLK - 1) / TOK_PER_BLK;   // 4096
    embed_gather_kernel<<<blocks, 128>>>(ids, w, out, n_tokens);
}